// round 16
// baseline (speedup 1.0000x reference)
#include <cuda_runtime.h>
#include <cuda_fp16.h>
#include <math.h>

#define BB   128
#define SS   400
#define EE   512
#define TT   300
#define VV   30
#define EMBD 256
#define H1   512
#define H2   128
#define PP   128
#define G1   2048
#define G2   512
#define NCTA 128
#define NTHR 256
#define PRED_N (BB*VV*TT)

typedef unsigned long long u64;

// ---------------- device scratch (no cudaMalloc allowed) ----------------
// Gate-interleaved column order everywhere: jnew = 4*h + gate (gate: 0=i,1=f,2=g,3=o)
__device__ __align__(16) __half  g_keysh [BB*SS*PP];   // fp16 keys [b][s][p]
__device__ __align__(16) __half  g_valsh [BB*SS*PP];   // fp16 values [b][s][p]
__device__ __align__(16) __half  g_W1h   [640*G1];     // [k][jnew]: k<128 ctx cols, else W_hh1
__device__ __align__(16) __half  g_W2h   [640*G2];     // [k][jnew]: k<512 W_ih2, else W_hh2
__device__ __align__(16) float   g_MembT [G1*32];      // [jnew][tok]
__device__ __align__(16) float   g_b2    [G2];         // [jnew] b_ih2+b_hh2
__device__ __align__(16) float   g_part1 [2][G1*BB];   // LSTM1 partials, [kh][jnew][b]
__device__ __align__(16) float   g_part2 [4][G2*BB];   // LSTM2 partials, [ks][jnew][b]
// xT rows: [0,128) ctx | [128,640) h1 slot0 | [640,1152) h1 slot1 | [1152,1280) h2prev
__device__ __align__(16) float   g_xT    [1280*BB];
__device__ __align__(16) float   g_c1T   [H1*BB];      // [h][b], single-CTA owner
__device__ __align__(16) float   g_c2    [BB*H2];      // [b][h], single-CTA owner
__device__ __align__(16) unsigned g_flags[256];        // packed: 128 flags in 2 lines
__device__ unsigned g_pflags[NCTA*32];                 // AB pairwise flags (padded)

__device__ __forceinline__ float sigf(float x) { return 1.f / (1.f + expf(-x)); }

__device__ __forceinline__ u64 ffma2(u64 a, u64 b, u64 c) {
    u64 d; asm("fma.rn.f32x2 %0,%1,%2,%3;" : "=l"(d) : "l"(a), "l"(b), "l"(c)); return d;
}
__device__ __forceinline__ u64 pack2(float v) {
    u64 d; asm("mov.b64 %0,{%1,%1};" : "=l"(d) : "f"(v)); return d;
}
__device__ __forceinline__ float2 unpk(u64 d) {
    float2 f; asm("mov.b64 {%0,%1},%2;" : "=f"(f.x), "=f"(f.y) : "l"(d)); return f;
}
__device__ __forceinline__ unsigned ld_acq(unsigned* p) {
    unsigned v; asm volatile("ld.acquire.gpu.u32 %0, [%1];" : "=r"(v) : "l"(p) : "memory"); return v;
}
__device__ __forceinline__ void st_rel(unsigned* p, unsigned v) {
    asm volatile("st.release.gpu.u32 [%0], %1;" :: "l"(p), "r"(v) : "memory");
}
__device__ __forceinline__ uint4 ldv4(const unsigned* p) {
    uint4 v;
    asm volatile("ld.volatile.global.v4.u32 {%0,%1,%2,%3}, [%4];"
                 : "=r"(v.x), "=r"(v.y), "=r"(v.z), "=r"(v.w) : "l"(p) : "memory");
    return v;
}

// ---- low-traffic grid barrier: packed flags, 32 pollers x 4 flags/load ----
// Producers st.release.gpu (orders their STG data into L2 first).
// All cross-CTA mutable data is read via __ldcg (L2 direct), so volatile L2
// polling is sufficient; no fence, no CCTL.IVALL, L1 stays warm.
__device__ __forceinline__ void gridbar(int cta, int tid, unsigned& epoch) {
    epoch++;
    __syncthreads();
    if (tid == 0) st_rel(&g_flags[cta], epoch);
    if (tid < 32) {
        const unsigned* p = g_flags + tid * 4;
        uint4 v = ldv4(p);
        while (v.x < epoch || v.y < epoch || v.z < epoch || v.w < epoch) {
            __nanosleep(40);
            v = ldv4(p);
        }
    }
    __syncthreads();
}

// ---------------- precompute kernels ----------------
__global__ void pack_kernel(const float* __restrict__ Wih1, const float* __restrict__ Whh1,
                            const float* __restrict__ Wih2, const float* __restrict__ Whh2,
                            const float* __restrict__ bih2, const float* __restrict__ bhh2) {
    int gid = blockIdx.x * blockDim.x + threadIdx.x;
    if (gid < 640 * G1) {
        int k = gid / G1, jn = gid % G1;
        int h = jn >> 2, gate = jn & 3, jo = gate * H1 + h;
        float w = (k < PP) ? Wih1[jo * (EMBD + PP) + k] : Whh1[jo * H1 + (k - PP)];
        g_W1h[gid] = __float2half(w);
    } else if (gid < 640 * G1 + 640 * G2) {
        int g2 = gid - 640 * G1;
        int k = g2 / G2, jn = g2 % G2;
        int h = jn >> 2, gate = jn & 3, jo = gate * H2 + h;
        float w = (k < H1) ? Wih2[jo * H1 + k] : Whh2[jo * H2 + (k - H1)];
        g_W2h[g2] = __float2half(w);
    } else {
        int jn = gid - 640 * G1 - 640 * G2;
        if (jn < G2) {
            int h = jn >> 2, gate = jn & 3, jo = gate * H2 + h;
            g_b2[jn] = bih2[jo] + bhh2[jo];
        }
    }
}

__global__ void memb_kernel(const float* __restrict__ emb, const float* __restrict__ Wih1,
                            const float* __restrict__ bih1, const float* __restrict__ bhh1) {
    int gid = blockIdx.x * blockDim.x + threadIdx.x;
    if (gid >= VV * G1) return;
    int v = gid / G1, jn = gid % G1;
    int h = jn >> 2, gate = jn & 3, jo = gate * H1 + h;
    const float* er = emb + v * EMBD;
    const float* wr = Wih1 + jo * (EMBD + PP) + PP;
    float s = bih1[jo] + bhh1[jo];
    for (int k = 0; k < EMBD; k++) s += er[k] * wr[k];
    g_MembT[jn * 32 + v] = s;
}

// keys/values: out[row][p] = enc[row] . W[p] + bias[p] (f32x2 compute, fp16 store)
__global__ __launch_bounds__(256) void kv_kernel(
    const float* __restrict__ enc,
    const float* __restrict__ Wk, const float* __restrict__ bk,
    const float* __restrict__ Wv, const float* __restrict__ bv) {
    __align__(16) __shared__ float sh[10752];
    float* xs = sh;          // [64][132]  (b contiguous per k-row)
    float* ws = sh + 8448;   // [64][36]
    int rt = blockIdx.x;
    int m = blockIdx.y;
    int mat = m >> 2, jt = m & 3;
    const float* W    = mat ? Wv : Wk;
    const float* bias = mat ? bv : bk;
    __half* outh      = mat ? g_valsh : g_keysh;
    int r0 = rt * 128, j0 = jt * 32;
    int tid = threadIdx.x;
    int tb = tid >> 3, tj = tid & 7;
    u64 acc[2][4];
    #pragma unroll
    for (int i = 0; i < 2; i++)
        #pragma unroll
        for (int c = 0; c < 4; c++) acc[i][c] = 0ull;
    for (int kc = 0; kc < EE; kc += 64) {
        #pragma unroll
        for (int i = 0; i < 32; i++) {
            int lin = i * 256 + tid;
            int br = lin >> 6, kk = lin & 63;
            xs[kk * 132 + br] = enc[(size_t)(r0 + br) * EE + kc + kk];
        }
        #pragma unroll
        for (int i = 0; i < 8; i++) {
            int lin = i * 256 + tid;
            int jj = lin >> 6, kk = lin & 63;
            ws[kk * 36 + jj] = W[(j0 + jj) * EE + kc + kk];
        }
        __syncthreads();
        #pragma unroll 16
        for (int kk = 0; kk < 64; kk++) {
            ulonglong2 xv = *(const ulonglong2*)&xs[kk * 132 + tb * 4];   // b-pairs
            float4 wv = *(const float4*)&ws[kk * 36 + tj * 4];
            u64 w0 = pack2(wv.x), w1 = pack2(wv.y), w2 = pack2(wv.z), w3 = pack2(wv.w);
            acc[0][0] = ffma2(xv.x, w0, acc[0][0]);
            acc[0][1] = ffma2(xv.x, w1, acc[0][1]);
            acc[0][2] = ffma2(xv.x, w2, acc[0][2]);
            acc[0][3] = ffma2(xv.x, w3, acc[0][3]);
            acc[1][0] = ffma2(xv.y, w0, acc[1][0]);
            acc[1][1] = ffma2(xv.y, w1, acc[1][1]);
            acc[1][2] = ffma2(xv.y, w2, acc[1][2]);
            acc[1][3] = ffma2(xv.y, w3, acc[1][3]);
        }
        __syncthreads();
    }
    float4 bb = *(const float4*)&bias[j0 + tj * 4];
    int co = j0 + tj * 4;
    #pragma unroll
    for (int r = 0; r < 4; r++) {
        int pr = r >> 1, hi = r & 1;
        float2 f0 = unpk(acc[pr][0]);
        float2 f1 = unpk(acc[pr][1]);
        float2 f2 = unpk(acc[pr][2]);
        float2 f3 = unpk(acc[pr][3]);
        float v0 = (hi ? f0.y : f0.x) + bb.x;
        float v1 = (hi ? f1.y : f1.x) + bb.y;
        float v2 = (hi ? f2.y : f2.x) + bb.z;
        float v3 = (hi ? f3.y : f3.x) + bb.w;
        __half* dst = outh + (size_t)(r0 + tb * 4 + r) * PP + co;
        *(__half2*)(dst)     = __floats2half2_rn(v0, v1);
        *(__half2*)(dst + 2) = __floats2half2_rn(v2, v3);
    }
}

// zero states + both h1 slots + h2prev, context0 = mean_s(values), reset flags
__global__ void init_kernel() {
    int gid = blockIdx.x * blockDim.x + threadIdx.x;
    if (gid < 1152 * BB) g_xT[128 * BB + gid] = 0.f;   // h1 slots + h2prev
    if (gid < H1 * BB)  g_c1T[gid] = 0.f;
    if (gid < BB * H2)  g_c2[gid] = 0.f;
    if (gid < BB * PP) {
        int b = gid >> 7, p = gid & 127;
        float s = 0.f;
        for (int ss = 0; ss < SS; ss++) s += __half2float(g_valsh[((size_t)b * SS + ss) * PP + p]);
        g_xT[p * BB + b] = s * (1.f / SS);
    }
    if (gid < 256)  g_flags[gid] = 0u;
    if (gid < NCTA) g_pflags[gid * 32] = 0u;
}

// ---------------- the persistent decode loop ----------------
__global__ __launch_bounds__(NTHR, 1) void loop_kernel(
    const int* __restrict__ y, const int* __restrict__ lens,
    const float* __restrict__ Wq, const float* __restrict__ bq,
    const float* __restrict__ emb, const float* __restrict__ bout,
    float* __restrict__ out) {
    __align__(16) __shared__ float sh[10368];
    const int cta = blockIdx.x;
    const int tid = threadIdx.x;
    unsigned epoch = 0u;

    for (int t = 0; t < TT; t++) {
        const int RA = 128 + (t & 1) * 512;          // h1 read slot (rows)
        const int WA = 128 + ((t & 1) ^ 1) * 512;    // h1 write slot (rows)

        // ==== Stage AB: LSTM1 GEMM (2-way k-split, pairwise sync) + fused cell ====
        {
            float* xs = sh;          // [64][128]
            float* ws = sh + 8192;   // [64][32]
            const int jt = cta >> 1, kh = cta & 1;
            const int j0 = jt * 32, kb = kh * 320;
            const int tj = tid >> 4, tb = tid & 15;   // 2 j per tj, 8 b per tb
            u64 acc[2][4];
            #pragma unroll
            for (int i = 0; i < 2; i++)
                #pragma unroll
                for (int c = 0; c < 4; c++) acc[i][c] = 0ull;
            for (int kc = 0; kc < 320; kc += 64) {
                #pragma unroll
                for (int i = 0; i < 8; i++) {
                    int lin = i * 256 + tid;
                    int kk = lin >> 5, x4 = (lin & 31) * 4;
                    int k = kb + kc + kk;
                    int row = (k < 128) ? k : (RA - 128 + k);
                    *(float4*)&xs[kk * 128 + x4] = __ldcg((const float4*)&g_xT[row * BB + x4]);
                }
                #pragma unroll
                for (int i = 0; i < 4; i++) {
                    int lin = i * 256 + tid;
                    int kk = lin >> 4, x2 = (lin & 15) * 2;
                    __half2 hv = *(const __half2*)(g_W1h + (size_t)(kb + kc + kk) * G1 + j0 + x2);
                    *(float2*)&ws[kk * 32 + x2] = __half22float2(hv);
                }
                __syncthreads();
                #pragma unroll
                for (int kk = 0; kk < 64; kk++) {
                    float2 wv = *(const float2*)&ws[kk * 32 + tj * 2];
                    u64 w0 = pack2(wv.x), w1 = pack2(wv.y);
                    ulonglong2 xa = *(const ulonglong2*)&xs[kk * 128 + tb * 8];
                    ulonglong2 xb = *(const ulonglong2*)&xs[kk * 128 + tb * 8 + 4];
                    acc[0][0] = ffma2(xa.x, w0, acc[0][0]);
                    acc[0][1] = ffma2(xa.y, w0, acc[0][1]);
                    acc[0][2] = ffma2(xb.x, w0, acc[0][2]);
                    acc[0][3] = ffma2(xb.y, w0, acc[0][3]);
                    acc[1][0] = ffma2(xa.x, w1, acc[1][0]);
                    acc[1][1] = ffma2(xa.y, w1, acc[1][1]);
                    acc[1][2] = ffma2(xb.x, w1, acc[1][2]);
                    acc[1][3] = ffma2(xb.y, w1, acc[1][3]);
                }
                __syncthreads();
            }
            float* dst = g_part1[kh];
            #pragma unroll
            for (int jj = 0; jj < 2; jj++) {
                int j = j0 + tj * 2 + jj;
                *(ulonglong2*)&dst[(size_t)j * BB + tb * 8]     = make_ulonglong2(acc[jj][0], acc[jj][1]);
                *(ulonglong2*)&dst[(size_t)j * BB + tb * 8 + 4] = make_ulonglong2(acc[jj][2], acc[jj][3]);
            }
            __syncthreads();
            if (tid == 0) {
                st_rel(&g_pflags[cta * 32], (unsigned)(t + 1));
                while (ld_acq(&g_pflags[(cta ^ 1) * 32]) < (unsigned)(t + 1)) { }
            }
            __syncthreads();
            // fused LSTM1 cell for this CTA's 4 h values (all 128 batches)
            int* stok = (int*)(sh + 10240);
            if (tid < BB) stok[tid] = (t == 0) ? 0 : y[tid * TT + t];
            __syncthreads();
            const int hbase = jt * 8 + kh * 4;
            #pragma unroll
            for (int e = 0; e < 2; e++) {
                int idx = e * 256 + tid;
                int h = hbase + (idx >> 7), b = idx & 127;
                int tok = stok[b];
                int j4 = 4 * h;
                float gi = g_MembT[(size_t)j4 * 32 + tok]
                         + __ldcg(&g_part1[0][(size_t)j4 * BB + b])
                         + __ldcg(&g_part1[1][(size_t)j4 * BB + b]);
                float gf = g_MembT[(size_t)(j4 + 1) * 32 + tok]
                         + __ldcg(&g_part1[0][(size_t)(j4 + 1) * BB + b])
                         + __ldcg(&g_part1[1][(size_t)(j4 + 1) * BB + b]);
                float gg = g_MembT[(size_t)(j4 + 2) * 32 + tok]
                         + __ldcg(&g_part1[0][(size_t)(j4 + 2) * BB + b])
                         + __ldcg(&g_part1[1][(size_t)(j4 + 2) * BB + b]);
                float go = g_MembT[(size_t)(j4 + 3) * 32 + tok]
                         + __ldcg(&g_part1[0][(size_t)(j4 + 3) * BB + b])
                         + __ldcg(&g_part1[1][(size_t)(j4 + 3) * BB + b]);
                float c = sigf(gf) * g_c1T[h * BB + b] + sigf(gi) * tanhf(gg);
                g_c1T[h * BB + b] = c;
                g_xT[(WA + h) * BB + b] = sigf(go) * tanhf(c);
            }
        }
        gridbar(cta, tid, epoch);

        // ==== Stage B2: LSTM2 gates over x2=[h1;h2prev], K=640, 4-way k-split ====
        {
            float* xs = sh;          // [32][128]
            float* ws = sh + 4096;   // [32][16]
            const int jt = cta >> 2, ks = cta & 3;
            const int j0 = jt * 16, kb = ks * 160;
            const int tj = tid >> 5, tb = tid & 31;   // 2 j per tj, 4 b per tb
            u64 acc[2][2];
            acc[0][0] = acc[0][1] = acc[1][0] = acc[1][1] = 0ull;
            for (int kc = 0; kc < 160; kc += 32) {
                #pragma unroll
                for (int i = 0; i < 4; i++) {
                    int lin = i * 256 + tid;
                    int kk = lin >> 5, x4 = (lin & 31) * 4;
                    int kg = kb + kc + kk;
                    int row = (kg < 512) ? (WA + kg) : (640 + kg);   // 1152 + (kg-512)
                    *(float4*)&xs[kk * 128 + x4] = __ldcg((const float4*)&g_xT[row * BB + x4]);
                }
                {
                    int kk = tid >> 3, x2 = (tid & 7) * 2;
                    __half2 hv = *(const __half2*)(g_W2h + (size_t)(kb + kc + kk) * G2 + j0 + x2);
                    *(float2*)&ws[kk * 16 + x2] = __half22float2(hv);
                }
                __syncthreads();
                #pragma unroll
                for (int kk = 0; kk < 32; kk++) {
                    float2 wv = *(const float2*)&ws[kk * 16 + tj * 2];
                    u64 w0 = pack2(wv.x), w1 = pack2(wv.y);
                    ulonglong2 xa = *(const ulonglong2*)&xs[kk * 128 + tb * 4];
                    acc[0][0] = ffma2(xa.x, w0, acc[0][0]);
                    acc[0][1] = ffma2(xa.y, w0, acc[0][1]);
                    acc[1][0] = ffma2(xa.x, w1, acc[1][0]);
                    acc[1][1] = ffma2(xa.y, w1, acc[1][1]);
                }
                __syncthreads();
            }
            float* dst = g_part2[ks];
            #pragma unroll
            for (int jj = 0; jj < 2; jj++) {
                int j = j0 + tj * 2 + jj;
                *(ulonglong2*)&dst[(size_t)j * BB + tb * 4] = make_ulonglong2(acc[jj][0], acc[jj][1]);
            }
        }
        gridbar(cta, tid, epoch);

        // ==== Stage C: per-batch CTA: LSTM2 cell, q, attention, context, logits ====
        {
            const int b = cta;
            float* sg   = sh;            // 512 (gate-interleaved)
            float* h2s  = sh + 512;      // 128
            float* qs   = sh + 640;      // 128 (reused as ctx)
            float* satt = sh + 768;      // 400
            float* red  = sh + 1168;     // 8
            float* sinv = sh + 1176;     // 1
            float* cred = sh + 1184;     // 512

            #pragma unroll
            for (int e = 0; e < 2; e++) {
                int j = e * 256 + tid;
                float s = g_b2[j];
                #pragma unroll
                for (int ks = 0; ks < 4; ks++) s += __ldcg(&g_part2[ks][(size_t)j * BB + b]);
                sg[j] = s;
            }
            __syncthreads();
            if (tid < H2) {
                float4 g4 = *(const float4*)&sg[4 * tid];   // i,f,g,o
                float c = sigf(g4.y) * g_c2[b * H2 + tid] + sigf(g4.x) * tanhf(g4.z);
                g_c2[b * H2 + tid] = c;
                float hh = sigf(g4.w) * tanhf(c);
                g_xT[(1152 + tid) * BB + b] = hh;   // h2prev for next step
                h2s[tid] = hh;
            }
            __syncthreads();
            if (tid < PP) {
                const float4* wr = (const float4*)(Wq + tid * H2);
                const float4* h4 = (const float4*)h2s;
                float s = bq[tid];
                #pragma unroll 8
                for (int k4 = 0; k4 < 32; k4++) {
                    float4 w = wr[k4], h = h4[k4];
                    s += w.x*h.x + w.y*h.y + w.z*h.z + w.w*h.w;
                }
                qs[tid] = s;
            }
            __syncthreads();
            int lenb = lens[b];
            const float scale = 0.08838834764831845f;   // 1/sqrt(128)
            float pmax = -3.4e38f;
            for (int s = tid; s < SS; s += NTHR) {
                const uint4* kr = (const uint4*)(g_keysh + (size_t)(b * SS + s) * PP);
                const float4* q4 = (const float4*)qs;
                float d = 0.f;
                #pragma unroll
                for (int i = 0; i < 16; i++) {
                    uint4 u = kr[i];
                    const __half2* hp = (const __half2*)&u;
                    float2 f0 = __half22float2(hp[0]);
                    float2 f1 = __half22float2(hp[1]);
                    float2 f2 = __half22float2(hp[2]);
                    float2 f3 = __half22float2(hp[3]);
                    float4 qa = q4[2 * i], qb = q4[2 * i + 1];
                    d += f0.x*qa.x + f0.y*qa.y + f1.x*qa.z + f1.y*qa.w
                       + f2.x*qb.x + f2.y*qb.y + f3.x*qb.z + f3.y*qb.w;
                }
                d *= scale;
                if (s >= lenb) d = -1e9f;
                satt[s] = d;
                pmax = fmaxf(pmax, d);
            }
            float m = pmax;
            #pragma unroll
            for (int o = 16; o > 0; o >>= 1) m = fmaxf(m, __shfl_xor_sync(0xffffffffu, m, o));
            if ((tid & 31) == 0) red[tid >> 5] = m;
            __syncthreads();
            float mx = red[0];
            #pragma unroll
            for (int i = 1; i < 8; i++) mx = fmaxf(mx, red[i]);
            __syncthreads();
            float psum = 0.f;
            for (int s = tid; s < SS; s += NTHR) {
                float e = expf(satt[s] - mx);
                satt[s] = e;
                psum += e;
            }
            #pragma unroll
            for (int o = 16; o > 0; o >>= 1) psum += __shfl_xor_sync(0xffffffffu, psum, o);
            if ((tid & 31) == 0) red[tid >> 5] = psum;
            __syncthreads();
            if (tid == 0) {
                float s = 0.f;
                #pragma unroll
                for (int i = 0; i < 8; i++) s += red[i];
                sinv[0] = 1.f / s;
            }
            __syncthreads();
            float inv = sinv[0];
            {
                int p2 = tid & 63, sq = tid >> 6;    // 4 quarters of 100 s each
                const __half2* vp = (const __half2*)g_valsh + ((size_t)b * SS + sq * 100) * 64 + p2;
                float cx0 = 0.f, cy0 = 0.f, cx1 = 0.f, cy1 = 0.f;
                #pragma unroll 4
                for (int s = 0; s < 100; s += 2) {
                    float2 v0 = __half22float2(vp[(size_t)s * 64]);
                    float2 v1 = __half22float2(vp[(size_t)(s + 1) * 64]);
                    float a0 = satt[sq * 100 + s];
                    float a1 = satt[sq * 100 + s + 1];
                    cx0 = fmaf(a0, v0.x, cx0); cy0 = fmaf(a0, v0.y, cy0);
                    cx1 = fmaf(a1, v1.x, cx1); cy1 = fmaf(a1, v1.y, cy1);
                }
                cred[sq * 128 + p2 * 2]     = cx0 + cx1;
                cred[sq * 128 + p2 * 2 + 1] = cy0 + cy1;
            }
            __syncthreads();
            if (tid < PP) {
                float c = (cred[tid] + cred[128 + tid] + cred[256 + tid] + cred[384 + tid]) * inv;
                g_xT[tid * BB + b] = c;   // ctx for next step
                qs[tid] = c;
            }
            __syncthreads();
            // logits: 240 threads (30 v x 8 chunks of 32), shuffle reduce per v
            {
                int v = tid >> 3, ch = tid & 7;
                float lg = 0.f;
                if (v < VV) {
                    const float* er = emb + v * EMBD + ch * 32;
                    const float* src = (ch < 4) ? (qs + ch * 32) : (h2s + (ch - 4) * 32);
                    #pragma unroll 8
                    for (int e = 0; e < 32; e++) lg += src[e] * er[e];
                }
                lg += __shfl_down_sync(0xffffffffu, lg, 4, 8);
                lg += __shfl_down_sync(0xffffffffu, lg, 2, 8);
                lg += __shfl_down_sync(0xffffffffu, lg, 1, 8);
                if (v < VV && ch == 0)
                    out[((size_t)b * VV + v) * TT + t] = lg + bout[v];   // predictions [B,V,T]
            }
            if (b == 0) {
                for (int s = tid; s < SS; s += NTHR)
                    out[PRED_N + t * SS + s] = satt[s] * inv;  // attention_plot [T,S]
            }
        }
        gridbar(cta, tid, epoch);
    }
}

// ---------------- launch ----------------
extern "C" void kernel_launch(void* const* d_in, const int* in_sizes, int n_in,
                              void* d_out, int out_size) {
    (void)in_sizes; (void)n_in; (void)out_size;
    const float* enc  = (const float*)d_in[0];
    const int*   lens = (const int*)d_in[1];
    const int*   y    = (const int*)d_in[2];
    const float* emb  = (const float*)d_in[3];
    const float* Wih1 = (const float*)d_in[4];
    const float* Whh1 = (const float*)d_in[5];
    const float* bih1 = (const float*)d_in[6];
    const float* bhh1 = (const float*)d_in[7];
    const float* Wih2 = (const float*)d_in[8];
    const float* Whh2 = (const float*)d_in[9];
    const float* bih2 = (const float*)d_in[10];
    const float* bhh2 = (const float*)d_in[11];
    const float* Wk   = (const float*)d_in[12];
    const float* bk   = (const float*)d_in[13];
    const float* Wv   = (const float*)d_in[14];
    const float* bv   = (const float*)d_in[15];
    const float* Wq   = (const float*)d_in[16];
    const float* bq   = (const float*)d_in[17];
    const float* bout = (const float*)d_in[18];
    float* out = (float*)d_out;

    int pack_n = 640 * G1 + 640 * G2 + G2;
    pack_kernel<<<(pack_n + 255) / 256, 256>>>(Wih1, Whh1, Wih2, Whh2, bih2, bhh2);
    memb_kernel<<<(VV * G1 + 255) / 256, 256>>>(emb, Wih1, bih1, bhh1);
    kv_kernel<<<dim3(400, 8), 256>>>(enc, Wk, bk, Wv, bv);
    init_kernel<<<640, 256>>>();
    loop_kernel<<<NCTA, NTHR>>>(y, lens, Wq, bq, emb, bout, out);
}